// round 4
// baseline (speedup 1.0000x reference)
#include <cuda_runtime.h>
#include <cuda_fp16.h>
#include <cstdint>
#include <math.h>

#define BB 512
#define RR 1152
#define OO 16
#define CO 160
#define II 8

#define CLUSTER 8
#define RPC (RR / CLUSTER)   // 144 rows per CTA
#define CHUNK 8              // rows per warp iteration
#define NCH (RPC / CHUNK)    // 18 chunks per CTA

// u_hat fp16 [b][r][co], 189 MB (__device__ global: sanctioned scratch)
__device__ uint4 g_uhat4[(size_t)BB * RR * CO / 8];

// ---------------------------------------------------------------------------
// K1: u_hat[b,r,c,o] = sum_i W[r,c,o,i] * x[b,r,i], stored fp16 [b][r][co].
// Block per r; W register-resident; x[:,r,:] staged in smem.
// ---------------------------------------------------------------------------
__global__ __launch_bounds__(256) void uhat_kernel(const float* __restrict__ x,
                                                   const float* __restrict__ W) {
    const int r = blockIdx.x;
    const int tid = threadIdx.x;
    const int w = tid >> 5;
    const int l = tid & 31;

    __shared__ float4 xs4[BB * 2];  // 16 KB: x[:, r, :]

    for (int idx = tid; idx < BB * 2; idx += 256)
        xs4[idx] = reinterpret_cast<const float4*>(x)[(size_t)(idx >> 1) * (RR * 2) + r * 2 + (idx & 1)];

    const float4* W4 = reinterpret_cast<const float4*>(W + (size_t)r * CO * II);
    float4 wA[3][4];
#pragma unroll
    for (int s = 0; s < 3; s++) {
        if (s < 2 || l < 16) {
            int p = s * 32 + l;
#pragma unroll
            for (int q = 0; q < 4; q++) wA[s][q] = W4[p * 4 + q];
        }
    }
    __syncthreads();

    for (int b = w; b < BB; b += 8) {
        const float4 xa = xs4[b * 2 + 0];
        const float4 xb = xs4[b * 2 + 1];
        __half2* outp = reinterpret_cast<__half2*>(g_uhat4 + ((size_t)b * RR + r) * (CO / 8));
#pragma unroll
        for (int s = 0; s < 3; s++) {
            if (s < 2 || l < 16) {
                float u0 = wA[s][0].x * xa.x + wA[s][0].y * xa.y + wA[s][0].z * xa.z + wA[s][0].w * xa.w +
                           wA[s][1].x * xb.x + wA[s][1].y * xb.y + wA[s][1].z * xb.z + wA[s][1].w * xb.w;
                float u1 = wA[s][2].x * xa.x + wA[s][2].y * xa.y + wA[s][2].z * xa.z + wA[s][2].w * xa.w +
                           wA[s][3].x * xb.x + wA[s][3].y * xb.y + wA[s][3].z * xb.z + wA[s][3].w * xb.w;
                outp[s * 32 + l] = __floats2half2_rn(u0, u1);
            }
        }
    }
}

// ---------------------------------------------------------------------------
// Fused routing: 8-CTA cluster per batch element. Each CTA caches 144 rows
// (45KB fp16) in smem ONCE; all 3 routing iterations run from smem. Per-iter
// 160-float partial s is all-to-all broadcast via st.shared::cluster +
// one cluster barrier (double-buffered slots); squash computed redundantly.
//   iter0: weights = 0.1 exactly -> v0
//   iter1: logits = u.v0        -> vdot = v0+v1
//   iter2: logits = u.(v0+v1)   -> v2 -> dout (rank 0 writes)
// ---------------------------------------------------------------------------

// smem byte offsets (dynamic)
#define TILE_OFF 0                         // uint4[2880]       = 46080
#define PART_OFF 46080                     // f32[8][8][160]    = 40960
#define SLOT_OFF 87040                     // f32[2][8][160]    = 10240
#define VDOT_OFF 97280                     // f32[160]          = 640
#define SSM_OFF  97920                     // f32[160]          = 640
#define ESM_OFF  98560                     // f32[8][80]        = 2560
#define INV_OFF  101120                    // f32[8][8]         = 256
#define SMEM_BYTES 101376

__device__ __forceinline__ void st_cluster_f32(unsigned int laddr, unsigned int peer, float v) {
    asm volatile(
        "{ .reg .b32 ra; mapa.shared::cluster.u32 ra, %0, %1; "
        "st.shared::cluster.f32 [ra], %2; }"
        :: "r"(laddr), "r"(peer), "f"(v) : "memory");
}

__device__ __forceinline__ void cluster_sync_all() {
    asm volatile("barrier.cluster.arrive.aligned;" ::: "memory");
    asm volatile("barrier.cluster.wait.aligned;" ::: "memory");
}

__global__ __launch_bounds__(256, 2) __cluster_dims__(CLUSTER, 1, 1)
void route_fused(const float* __restrict__ bias, float* __restrict__ dout) {
    extern __shared__ char sm[];
    uint4* tile   = reinterpret_cast<uint4*>(sm + TILE_OFF);
    float* part   = reinterpret_cast<float*>(sm + PART_OFF);
    float* slot   = reinterpret_cast<float*>(sm + SLOT_OFF);
    float* vdot   = reinterpret_cast<float*>(sm + VDOT_OFF);
    float* s_sm   = reinterpret_cast<float*>(sm + SSM_OFF);
    float* e_sm   = reinterpret_cast<float*>(sm + ESM_OFF);
    float* inv_sm = reinterpret_cast<float*>(sm + INV_OFF);

    const int tid = threadIdx.x;
    const int w = tid >> 5;
    const int l = tid & 31;
    const int b = blockIdx.x / CLUSTER;
    unsigned int rank;
    asm("mov.u32 %0, %%cluster_ctarank;" : "=r"(rank));

    // ---- load this CTA's 144-row slice of u_hat[b] into smem (once) ----
    const uint4* src = g_uhat4 + ((size_t)b * RR + rank * RPC) * (CO / 8);
#pragma unroll 4
    for (int i = tid; i < RPC * CO / 8; i += 256) tile[i] = src[i];
    __syncthreads();

    // per-slot constants: task t = l+32j -> (row within chunk, q=2c+half)
    int rowj[5], qj[5];
#pragma unroll
    for (int j = 0; j < 5; j++) {
        int t = l + 32 * j;
        rowj[j] = t / 20;
        qj[j] = t % 20;
    }

    for (int round = 0; round < 3; round++) {
        __half2 v2[5][4];
        if (round > 0) {
#pragma unroll
            for (int j = 0; j < 5; j++) {
                const float* vq = vdot + qj[j] * 8;
#pragma unroll
                for (int k = 0; k < 4; k++)
                    v2[j][k] = __floats2half2_rn(vq[2 * k], vq[2 * k + 1]);
            }
        }

        float acc[5][8];
#pragma unroll
        for (int j = 0; j < 5; j++)
#pragma unroll
            for (int k = 0; k < 8; k++) acc[j][k] = 0.0f;

        for (int ch = w; ch < NCH; ch += 8) {
            const uint4* p = tile + ch * (CHUNK * CO / 8);
            uint4 uu[5];
#pragma unroll
            for (int j = 0; j < 5; j++) uu[j] = p[l + 32 * j];

            float wgt[5];
            if (round > 0) {
                float e[5];
#pragma unroll
                for (int j = 0; j < 5; j++) {
                    const __half2* u2 = reinterpret_cast<const __half2*>(&uu[j]);
                    __half2 p2 = __hmul2(u2[0], v2[j][0]);
                    p2 = __hfma2(u2[1], v2[j][1], p2);
                    p2 = __hfma2(u2[2], v2[j][2], p2);
                    p2 = __hfma2(u2[3], v2[j][3], p2);
                    unsigned int pu = __shfl_xor_sync(0xffffffffu, *reinterpret_cast<unsigned int*>(&p2), 1);
                    p2 = __hadd2(p2, *reinterpret_cast<__half2*>(&pu));
                    float lg = __low2float(p2) + __high2float(p2);
                    e[j] = __expf(lg);  // logits bounded; no max-sub needed
                }
                if (!(l & 1)) {
#pragma unroll
                    for (int j = 0; j < 5; j++) e_sm[w * 80 + (l >> 1) + 16 * j] = e[j];
                }
                __syncwarp();
                if (l < 8) {
                    float s = 0.0f;
#pragma unroll
                    for (int i = 0; i < 10; i++) s += e_sm[w * 80 + l * 10 + i];
                    inv_sm[w * 8 + l] = 1.0f / s;
                }
                __syncwarp();
#pragma unroll
                for (int j = 0; j < 5; j++) wgt[j] = e[j] * inv_sm[w * 8 + rowj[j]];
            }

#pragma unroll
            for (int j = 0; j < 5; j++) {
                const __half2* u2 = reinterpret_cast<const __half2*>(&uu[j]);
#pragma unroll
                for (int k = 0; k < 4; k++) {
                    float2 uf = __half22float2(u2[k]);
                    if (round == 0) {
                        acc[j][2 * k] += uf.x;
                        acc[j][2 * k + 1] += uf.y;
                    } else {
                        acc[j][2 * k] += wgt[j] * uf.x;
                        acc[j][2 * k + 1] += wgt[j] * uf.y;
                    }
                }
            }
        }

        // flush per-warp partials: part[w][row][co]
#pragma unroll
        for (int j = 0; j < 5; j++)
#pragma unroll
            for (int k = 0; k < 8; k++)
                part[(w * 8 + rowj[j]) * CO + qj[j] * 8 + k] = acc[j][k];
        __syncthreads();

        const int buf = round & 1;
        if (tid < CO) {
            float s = 0.0f;
#pragma unroll
            for (int i = 0; i < 64; i++) s += part[i * CO + tid];
            // broadcast this CTA's partial to all 8 CTAs' slot[buf][rank][tid]
            unsigned int laddr = (unsigned int)__cvta_generic_to_shared(&slot[(buf * 8 + rank) * CO + tid]);
#pragma unroll
            for (unsigned int pr = 0; pr < CLUSTER; pr++) st_cluster_f32(laddr, pr, s);
        }
        cluster_sync_all();

        if (tid < CO) {
            float s = 0.0f;
#pragma unroll
            for (int rk = 0; rk < CLUSTER; rk++) s += slot[(buf * 8 + rk) * CO + tid];
            if (round == 0) s *= 0.1f;  // softmax(0) = 1/10 exactly
            s += bias[tid];
            s_sm[tid] = s;
        }
        __syncthreads();

        if (tid < CO) {
            int c = tid >> 4;
            float nsq = 0.0f;
#pragma unroll
            for (int o = 0; o < OO; o++) {
                float t = s_sm[c * 16 + o];
                nsq += t * t;
            }
            float val = s_sm[tid] * (sqrtf(nsq) / (1.0f + nsq + 1e-8f));
            if (round == 0) vdot[tid] = val;                    // v0
            else if (round == 1) vdot[tid] += val;              // v0+v1
            else if (rank == 0) dout[b * CO + tid] = val;       // v2
        }
        __syncthreads();
    }
}

// ---------------------------------------------------------------------------
extern "C" void kernel_launch(void* const* d_in, const int* in_sizes, int n_in,
                              void* d_out, int out_size) {
    const float* x    = (const float*)d_in[0];  // [512,1152,8]
    const float* W    = (const float*)d_in[1];  // [1152,10,16,8]
    const float* bias = (const float*)d_in[2];  // [1,1,10,16]
    float* out = (float*)d_out;                 // [512,10,16]

    cudaFuncSetAttribute(route_fused, cudaFuncAttributeMaxDynamicSharedMemorySize, SMEM_BYTES);

    uhat_kernel<<<RR, 256>>>(x, W);
    route_fused<<<BB * CLUSTER, 256, SMEM_BYTES>>>(bias, out);
}